// round 1
// baseline (speedup 1.0000x reference)
#include <cuda_runtime.h>
#include <cuda_bf16.h>
#include <cstdint>

// Problem constants (fixed by setup_inputs)
#define BB 2
#define LL 4096
#define DD 1024
#define DI 1024
#define NS 16
#define RR 64
#define HH 4096
#define MM (BB*LL)          // 8192 rows
#define PROJC (RR + 2*NS)   // 96

// ---------------- scratch ( __device__ globals, no allocation ) -------------
__device__ float g_U   [(size_t)MM * DD];      // LN(gathered x)
__device__ float g_XZ  [(size_t)MM * 2 * DI];  // in_proj output (xi | z)
__device__ float g_XC  [(size_t)MM * DI];      // conv + silu
__device__ float g_PROJ[(size_t)MM * PROJC];   // x_proj output
__device__ float g_DT  [(size_t)MM * DI];      // softplus(dt)
__device__ float g_Y   [(size_t)MM * DI];      // scan output * silu(z)
__device__ float g_OUTP[(size_t)MM * DD];      // out_proj output
__device__ float g_XNEW[(size_t)MM * DD];      // x + scattered mamba out
__device__ float g_HN  [(size_t)MM * DD];      // LN(xnew)
__device__ float g_G   [(size_t)MM * HH];      // gelu(fc1)

// ---------------- helpers ---------------------------------------------------
__device__ __forceinline__ float silu_f(float x) {
    return x / (1.0f + __expf(-x));
}
__device__ __forceinline__ float gelu_tanh_f(float x) {
    float u = 0.7978845608028654f * (x + 0.044715f * x * x * x);
    return 0.5f * x * (1.0f + tanhf(u));
}
__device__ __forceinline__ float softplus_f(float x) {
    return (x > 20.0f) ? x : log1pf(expf(x));
}

// ---------------- LayerNorm (optional gather) -------------------------------
// one block (256 thr) per row of 1024
__global__ __launch_bounds__(256) void ln_kernel(
    const float* __restrict__ X, const int* __restrict__ gather,
    float* __restrict__ Out)
{
    int row = blockIdx.x;                 // 0..MM-1
    int b = row >> 12, t = row & (LL - 1);
    int src = gather ? ((b << 12) + gather[t]) : row;
    const float* xp = X + (size_t)src * DD;
    float* op = Out + (size_t)row * DD;
    __shared__ float sred[8];
    __shared__ float smv[2];
    int tid = threadIdx.x;

    float v[4];
    float s = 0.f;
#pragma unroll
    for (int i = 0; i < 4; i++) { v[i] = xp[tid + i * 256]; s += v[i]; }
#pragma unroll
    for (int o = 16; o; o >>= 1) s += __shfl_xor_sync(0xffffffffu, s, o);
    if ((tid & 31) == 0) sred[tid >> 5] = s;
    __syncthreads();
    if (tid < 8) {
        s = sred[tid];
#pragma unroll
        for (int o = 4; o; o >>= 1) s += __shfl_xor_sync(0xffu, s, o);
        if (tid == 0) smv[0] = s * (1.0f / DD);
    }
    __syncthreads();
    float mean = smv[0];
    float vs = 0.f;
#pragma unroll
    for (int i = 0; i < 4; i++) { float d = v[i] - mean; vs += d * d; }
#pragma unroll
    for (int o = 16; o; o >>= 1) vs += __shfl_xor_sync(0xffffffffu, vs, o);
    __syncthreads();
    if ((tid & 31) == 0) sred[tid >> 5] = vs;
    __syncthreads();
    if (tid < 8) {
        vs = sred[tid];
#pragma unroll
        for (int o = 4; o; o >>= 1) vs += __shfl_xor_sync(0xffu, vs, o);
        if (tid == 0) smv[1] = rsqrtf(vs * (1.0f / DD) + 1e-6f);
    }
    __syncthreads();
    float inv = smv[1];
#pragma unroll
    for (int i = 0; i < 4; i++) op[tid + i * 256] = (v[i] - mean) * inv;
}

// ---------------- SGEMM: C[m,n] = epi( sum_k A[m,k]*W[n,k] ) ---------------
// A: M x K row-major with leading dim lda.  W: N x K row-major.
// MODE 0: plain   1: gelu(acc+bias)   2: resid + acc + bias   3: softplus(acc+bias)
#define BM 128
#define BN 128
#define BK 8
#define TM 8
#define TN 8
template <int MODE>
__global__ __launch_bounds__(256) void sgemm_kernel(
    const float* __restrict__ A, int lda,
    const float* __restrict__ W,
    const float* __restrict__ bias,
    const float* __restrict__ resid,
    float* __restrict__ C,
    int M, int N, int K)
{
    __shared__ float As[BK][BM];
    __shared__ float Ws[BK][BN];
    int tid = threadIdx.x;
    int tx = tid & 15, ty = tid >> 4;
    int row0 = blockIdx.y * BM;
    int col0 = blockIdx.x * BN;

    int l_row = tid >> 1;          // 0..127
    int l_col = (tid & 1) * 4;     // 0 or 4

    float acc[TM][TN];
#pragma unroll
    for (int i = 0; i < TM; i++)
#pragma unroll
        for (int j = 0; j < TN; j++) acc[i][j] = 0.f;

    const float* Abase = A + (size_t)(row0 + l_row) * lda + l_col;
    int wn = col0 + l_row;
    const float* Wbase = W + (size_t)wn * K + l_col;
    bool wok = (wn < N);

    for (int k0 = 0; k0 < K; k0 += BK) {
        float4 av = *(const float4*)(Abase + k0);
        As[l_col + 0][l_row] = av.x;
        As[l_col + 1][l_row] = av.y;
        As[l_col + 2][l_row] = av.z;
        As[l_col + 3][l_row] = av.w;
        float4 wv = make_float4(0.f, 0.f, 0.f, 0.f);
        if (wok) wv = *(const float4*)(Wbase + k0);
        Ws[l_col + 0][l_row] = wv.x;
        Ws[l_col + 1][l_row] = wv.y;
        Ws[l_col + 2][l_row] = wv.z;
        Ws[l_col + 3][l_row] = wv.w;
        __syncthreads();
#pragma unroll
        for (int kk = 0; kk < BK; kk++) {
            float af[TM], wf[TN];
#pragma unroll
            for (int i = 0; i < TM; i++) af[i] = As[kk][ty * TM + i];
#pragma unroll
            for (int j = 0; j < TN; j++) wf[j] = Ws[kk][tx * TN + j];
#pragma unroll
            for (int i = 0; i < TM; i++)
#pragma unroll
                for (int j = 0; j < TN; j++) acc[i][j] = fmaf(af[i], wf[j], acc[i][j]);
        }
        __syncthreads();
    }

#pragma unroll
    for (int i = 0; i < TM; i++) {
        int row = row0 + ty * TM + i;
#pragma unroll
        for (int j = 0; j < TN; j++) {
            int col = col0 + tx * TN + j;
            if (col < N) {
                float v = acc[i][j];
                size_t oidx = (size_t)row * N + col;
                if (MODE == 1) v = gelu_tanh_f(v + bias[col]);
                else if (MODE == 2) v = resid[oidx] + v + bias[col];
                else if (MODE == 3) v = softplus_f(v + bias[col]);
                C[oidx] = v;
            }
        }
    }
}

// ---------------- depthwise causal conv (D_CONV=4) + silu -------------------
__global__ __launch_bounds__(256) void conv_silu_kernel(
    const float* __restrict__ XZ, const float* __restrict__ conv_w,
    const float* __restrict__ conv_b, float* __restrict__ XC)
{
    size_t idx = (size_t)blockIdx.x * blockDim.x + threadIdx.x;
    if (idx >= (size_t)MM * DI) return;
    int d = (int)(idx & (DI - 1));
    int m = (int)(idx >> 10);
    int t = m & (LL - 1);
    int mb = m - t;                       // batch base row
    float acc = conv_b[d];
#pragma unroll
    for (int k = 0; k < 4; k++) {
        int tt = t - 3 + k;
        if (tt >= 0)
            acc = fmaf(conv_w[d * 4 + k], XZ[(size_t)(mb + tt) * (2 * DI) + d], acc);
    }
    XC[idx] = silu_f(acc);
}

// ---------------- selective scan: warp per (b,d) ----------------------------
__global__ __launch_bounds__(256) void scan_kernel(
    const float* __restrict__ DT, const float* __restrict__ XC,
    const float* __restrict__ PROJ, const float* __restrict__ XZ,
    const float* __restrict__ A_log, const float* __restrict__ D_param,
    float* __restrict__ Y)
{
    int wg = (blockIdx.x * blockDim.x + threadIdx.x) >> 5;  // 0..2047
    int lane = threadIdx.x & 31;
    int b = wg >> 10;
    int d = wg & (DI - 1);
    bool act = lane < NS;
    float A_n = act ? -expf(A_log[d * NS + lane]) : 0.f;
    float Dp = D_param[d];

    const float* dtp = DT + (size_t)b * LL * DI + d;
    const float* xcp = XC + (size_t)b * LL * DI + d;
    const float* zp  = XZ + (size_t)b * LL * (2 * DI) + DI + d;
    const float* bcp = PROJ + (size_t)b * LL * PROJC + RR;
    float* yp = Y + (size_t)b * LL * DI + d;

    float h = 0.f;
    for (int t = 0; t < LL; t++) {
        float dt = __ldg(dtp);
        float xc = __ldg(xcp);
        float zv = __ldg(zp);
        float bcv = __ldg(bcp + lane);        // lanes 0-15: B[n], 16-31: C[n]
        float Cv = __shfl_down_sync(0xffffffffu, bcv, 16);
        float Bv = act ? bcv : 0.f;
        Cv = act ? Cv : 0.f;

        float dA = __expf(dt * A_n);
        h = fmaf(dA, h, dt * xc * Bv);
        float part = h * Cv;
#pragma unroll
        for (int o = 16; o; o >>= 1) part += __shfl_xor_sync(0xffffffffu, part, o);
        if (lane == 0) {
            float y = part + Dp * xc;
            *yp = y * silu_f(zv);
        }
        dtp += DI; xcp += DI; zp += 2 * DI; bcp += PROJC; yp += DI;
    }
}

// ---------------- residual add with gather ----------------------------------
__global__ __launch_bounds__(256) void add_gather_kernel(
    const float* __restrict__ X, const float* __restrict__ OUTP,
    const int* __restrict__ path_rev, float* __restrict__ XNEW)
{
    size_t idx = (size_t)blockIdx.x * blockDim.x + threadIdx.x;
    if (idx >= (size_t)MM * DD) return;
    int d = (int)(idx & (DD - 1));
    int m = (int)(idx >> 10);
    int b = m >> 12, t = m & (LL - 1);
    int src = (b << 12) + path_rev[t];
    XNEW[idx] = X[idx] + OUTP[(size_t)src * DD + d];
}

// ---------------- launch -----------------------------------------------------
extern "C" void kernel_launch(void* const* d_in, const int* in_sizes, int n_in,
                              void* d_out, int out_size)
{
    const float* x          = (const float*)d_in[0];
    const int*   path       = (const int*)  d_in[1];
    const int*   path_rev   = (const int*)  d_in[2];
    const float* in_proj_w  = (const float*)d_in[3];
    const float* conv_w     = (const float*)d_in[4];
    const float* conv_b     = (const float*)d_in[5];
    const float* x_proj_w   = (const float*)d_in[6];
    const float* dt_proj_w  = (const float*)d_in[7];
    const float* dt_proj_b  = (const float*)d_in[8];
    const float* A_log      = (const float*)d_in[9];
    const float* D_param    = (const float*)d_in[10];
    const float* out_proj_w = (const float*)d_in[11];
    const float* fc1_w      = (const float*)d_in[12];
    const float* fc1_b      = (const float*)d_in[13];
    const float* fc2_w      = (const float*)d_in[14];
    const float* fc2_b      = (const float*)d_in[15];
    float* out = (float*)d_out;

    float *U, *XZ, *XC, *PROJ, *DT, *Y, *OUTP, *XNEW, *HN, *G;
    cudaGetSymbolAddress((void**)&U,    g_U);
    cudaGetSymbolAddress((void**)&XZ,   g_XZ);
    cudaGetSymbolAddress((void**)&XC,   g_XC);
    cudaGetSymbolAddress((void**)&PROJ, g_PROJ);
    cudaGetSymbolAddress((void**)&DT,   g_DT);
    cudaGetSymbolAddress((void**)&Y,    g_Y);
    cudaGetSymbolAddress((void**)&OUTP, g_OUTP);
    cudaGetSymbolAddress((void**)&XNEW, g_XNEW);
    cudaGetSymbolAddress((void**)&HN,   g_HN);
    cudaGetSymbolAddress((void**)&G,    g_G);

    // 1. u = LN(x[:, path, :])
    ln_kernel<<<MM, 256>>>(x, path, U);

    // 2. xz = u @ in_proj_w^T   (8192 x 2048, K=1024)
    {
        dim3 grid(2 * DI / BN, MM / BM);
        sgemm_kernel<0><<<grid, 256>>>(U, DD, in_proj_w, nullptr, nullptr, XZ,
                                       MM, 2 * DI, DD);
    }

    // 3. conv + silu
    conv_silu_kernel<<<(int)(((size_t)MM * DI + 255) / 256), 256>>>(XZ, conv_w, conv_b, XC);

    // 4. proj = xc @ x_proj_w^T   (8192 x 96, K=1024)
    {
        dim3 grid((PROJC + BN - 1) / BN, MM / BM);
        sgemm_kernel<0><<<grid, 256>>>(XC, DI, x_proj_w, nullptr, nullptr, PROJ,
                                       MM, PROJC, DI);
    }

    // 5. dt = softplus(proj[:, :64] @ dt_proj_w^T + b)   (8192 x 1024, K=64, lda=96)
    {
        dim3 grid(DI / BN, MM / BM);
        sgemm_kernel<3><<<grid, 256>>>(PROJ, PROJC, dt_proj_w, dt_proj_b, nullptr, DT,
                                       MM, DI, RR);
    }

    // 6. selective scan -> Y = (scan + D*xc) * silu(z)
    scan_kernel<<<(BB * DI * 32) / 256, 256>>>(DT, XC, PROJ, XZ, A_log, D_param, Y);

    // 7. OUTP = Y @ out_proj_w^T   (8192 x 1024, K=1024)
    {
        dim3 grid(DD / BN, MM / BM);
        sgemm_kernel<0><<<grid, 256>>>(Y, DI, out_proj_w, nullptr, nullptr, OUTP,
                                       MM, DD, DI);
    }

    // 8. xnew = x + OUTP[:, path_rev, :]
    add_gather_kernel<<<(int)(((size_t)MM * DD + 255) / 256), 256>>>(x, OUTP, path_rev, XNEW);

    // 9. hn = LN(xnew)
    ln_kernel<<<MM, 256>>>(XNEW, nullptr, HN);

    // 10. G = gelu(hn @ fc1_w^T + fc1_b)   (8192 x 4096, K=1024)
    {
        dim3 grid(HH / BN, MM / BM);
        sgemm_kernel<1><<<grid, 256>>>(HN, DD, fc1_w, fc1_b, nullptr, G,
                                       MM, HH, DD);
    }

    // 11. out = xnew + G @ fc2_w^T + fc2_b   (8192 x 1024, K=4096)
    {
        dim3 grid(DD / BN, MM / BM);
        sgemm_kernel<2><<<grid, 256>>>(G, HH, fc2_w, fc2_b, XNEW, out,
                                       MM, DD, HH);
    }
}

// round 2
// speedup vs baseline: 2.2330x; 2.2330x over previous
#include <cuda_runtime.h>
#include <cuda_bf16.h>
#include <cstdint>

// Problem constants (fixed by setup_inputs)
#define BB 2
#define LL 4096
#define DD 1024
#define DI 1024
#define NS 16
#define RR 64
#define HH 4096
#define MM (BB*LL)          // 8192 rows
#define PROJC (RR + 2*NS)   // 96

// ---------------- scratch ( __device__ globals, no allocation ) -------------
__device__ float g_U   [(size_t)MM * DD];      // LN(gathered x)
__device__ float g_XZ  [(size_t)MM * 2 * DI];  // in_proj output (xi | z)
__device__ float g_XC  [(size_t)MM * DI];      // conv + silu
__device__ float g_PROJ[(size_t)MM * PROJC];   // x_proj output
__device__ float g_DT  [(size_t)MM * DI];      // softplus(dt)
__device__ float g_Y   [(size_t)MM * DI];      // scan output * silu(z)
__device__ float g_OUTP[(size_t)MM * DD];      // out_proj output
__device__ float g_XNEW[(size_t)MM * DD];      // x + scattered mamba out
__device__ float g_HN  [(size_t)MM * DD];      // LN(xnew)
__device__ float g_G   [(size_t)MM * HH];      // gelu(fc1)

// ---------------- helpers ---------------------------------------------------
__device__ __forceinline__ float silu_f(float x) {
    return x / (1.0f + __expf(-x));
}
__device__ __forceinline__ float gelu_tanh_f(float x) {
    float u = 0.7978845608028654f * (x + 0.044715f * x * x * x);
    return 0.5f * x * (1.0f + tanhf(u));
}
__device__ __forceinline__ float softplus_f(float x) {
    return (x > 20.0f) ? x : log1pf(expf(x));
}
__device__ __forceinline__ float to_tf32(float x) {
    uint32_t u;
    asm("cvt.rna.tf32.f32 %0, %1;" : "=r"(u) : "f"(x));
    return __uint_as_float(u);
}

// ---------------- LayerNorm (optional gather) -------------------------------
__global__ __launch_bounds__(256) void ln_kernel(
    const float* __restrict__ X, const int* __restrict__ gather,
    float* __restrict__ Out)
{
    int row = blockIdx.x;                 // 0..MM-1
    int b = row >> 12, t = row & (LL - 1);
    int src = gather ? ((b << 12) + gather[t]) : row;
    const float* xp = X + (size_t)src * DD;
    float* op = Out + (size_t)row * DD;
    __shared__ float sred[8];
    __shared__ float smv[2];
    int tid = threadIdx.x;

    float v[4];
    float s = 0.f;
#pragma unroll
    for (int i = 0; i < 4; i++) { v[i] = xp[tid + i * 256]; s += v[i]; }
#pragma unroll
    for (int o = 16; o; o >>= 1) s += __shfl_xor_sync(0xffffffffu, s, o);
    if ((tid & 31) == 0) sred[tid >> 5] = s;
    __syncthreads();
    if (tid < 8) {
        s = sred[tid];
#pragma unroll
        for (int o = 4; o; o >>= 1) s += __shfl_xor_sync(0xffu, s, o);
        if (tid == 0) smv[0] = s * (1.0f / DD);
    }
    __syncthreads();
    float mean = smv[0];
    float vs = 0.f;
#pragma unroll
    for (int i = 0; i < 4; i++) { float d = v[i] - mean; vs += d * d; }
#pragma unroll
    for (int o = 16; o; o >>= 1) vs += __shfl_xor_sync(0xffffffffu, vs, o);
    __syncthreads();
    if ((tid & 31) == 0) sred[tid >> 5] = vs;
    __syncthreads();
    if (tid < 8) {
        vs = sred[tid];
#pragma unroll
        for (int o = 4; o; o >>= 1) vs += __shfl_xor_sync(0xffu, vs, o);
        if (tid == 0) smv[1] = rsqrtf(vs * (1.0f / DD) + 1e-6f);
    }
    __syncthreads();
    float inv = smv[1];
#pragma unroll
    for (int i = 0; i < 4; i++) op[tid + i * 256] = (v[i] - mean) * inv;
}

// ---------------- TF32 tensor-core GEMM -------------------------------------
// C[m,n] = epi( sum_k A[m,k]*W[n,k] )
// A: M x K row-major, leading dim lda.  W: N x K row-major.
// MODE 0: plain   1: gelu(acc+bias)   2: resid + acc + bias   3: softplus(acc+bias)
// Tile: 128x128, BK=16, 8 warps (4m x 2n), warp tile 32x64.
// mma.sync.m16n8k8 tf32: per warp per BK: 2m x 8n x 2k = 32 mma.

__device__ __forceinline__ void mma_tf32(float c[4], const float a[4], const float b[2]) {
    asm volatile(
        "mma.sync.aligned.m16n8k8.row.col.f32.tf32.tf32.f32 "
        "{%0,%1,%2,%3}, {%4,%5,%6,%7}, {%8,%9}, {%0,%1,%2,%3};\n"
        : "+f"(c[0]), "+f"(c[1]), "+f"(c[2]), "+f"(c[3])
        : "r"(__float_as_uint(a[0])), "r"(__float_as_uint(a[1])),
          "r"(__float_as_uint(a[2])), "r"(__float_as_uint(a[3])),
          "r"(__float_as_uint(b[0])), "r"(__float_as_uint(b[1])));
}

#define PAD 20

template <int MODE>
__global__ __launch_bounds__(256, 2) void mma_gemm(
    const float* __restrict__ A, int lda,
    const float* __restrict__ W,
    const float* __restrict__ bias,
    const float* __restrict__ resid,
    float* __restrict__ C,
    int M, int N, int K)
{
    __shared__ float As[2][128][PAD];
    __shared__ float Ws[2][128][PAD];

    int tid  = threadIdx.x;
    int warp = tid >> 5, lane = tid & 31;
    int g = lane >> 2, t = lane & 3;
    int wm = warp >> 1, wn = warp & 1;     // 4 x 2 warp grid
    int row0 = blockIdx.y * 128;
    int col0 = blockIdx.x * 128;

    // global load mapping: thread -> (row, 8 consecutive k)
    int lrow = tid >> 1;
    int lk   = (tid & 1) * 8;
    const float* Ag = A + (size_t)(row0 + lrow) * lda + lk;
    bool wok = (col0 + lrow) < N;
    const float* Wg = W + (size_t)(col0 + lrow) * K + lk;

    float acc[2][8][4];
#pragma unroll
    for (int i = 0; i < 2; i++)
#pragma unroll
        for (int j = 0; j < 8; j++)
#pragma unroll
            for (int q = 0; q < 4; q++) acc[i][j][q] = 0.f;

    float4 pa0, pa1, pw0, pw1;

#define LOADG(k0)                                                         \
    {                                                                     \
        pa0 = *(const float4*)(Ag + (k0));                                \
        pa1 = *(const float4*)(Ag + (k0) + 4);                            \
        if (wok) {                                                        \
            pw0 = *(const float4*)(Wg + (k0));                            \
            pw1 = *(const float4*)(Wg + (k0) + 4);                        \
        } else {                                                          \
            pw0 = make_float4(0.f, 0.f, 0.f, 0.f);                        \
            pw1 = pw0;                                                    \
        }                                                                 \
    }

#define STORES(b)                                                         \
    {                                                                     \
        As[b][lrow][lk + 0] = to_tf32(pa0.x);                             \
        As[b][lrow][lk + 1] = to_tf32(pa0.y);                             \
        As[b][lrow][lk + 2] = to_tf32(pa0.z);                             \
        As[b][lrow][lk + 3] = to_tf32(pa0.w);                             \
        As[b][lrow][lk + 4] = to_tf32(pa1.x);                             \
        As[b][lrow][lk + 5] = to_tf32(pa1.y);                             \
        As[b][lrow][lk + 6] = to_tf32(pa1.z);                             \
        As[b][lrow][lk + 7] = to_tf32(pa1.w);                             \
        Ws[b][lrow][lk + 0] = to_tf32(pw0.x);                             \
        Ws[b][lrow][lk + 1] = to_tf32(pw0.y);                             \
        Ws[b][lrow][lk + 2] = to_tf32(pw0.z);                             \
        Ws[b][lrow][lk + 3] = to_tf32(pw0.w);                             \
        Ws[b][lrow][lk + 4] = to_tf32(pw1.x);                             \
        Ws[b][lrow][lk + 5] = to_tf32(pw1.y);                             \
        Ws[b][lrow][lk + 6] = to_tf32(pw1.z);                             \
        Ws[b][lrow][lk + 7] = to_tf32(pw1.w);                             \
    }

#define COMPUTE(b)                                                        \
    {                                                                     \
        _Pragma("unroll")                                                 \
        for (int ks = 0; ks < 16; ks += 8) {                              \
            float af[2][4], bf[8][2];                                     \
            _Pragma("unroll")                                             \
            for (int i = 0; i < 2; i++) {                                 \
                int m0 = wm * 32 + i * 16;                                \
                af[i][0] = As[b][m0 + g][ks + t];                         \
                af[i][1] = As[b][m0 + g + 8][ks + t];                     \
                af[i][2] = As[b][m0 + g][ks + t + 4];                     \
                af[i][3] = As[b][m0 + g + 8][ks + t + 4];                 \
            }                                                             \
            _Pragma("unroll")                                             \
            for (int j = 0; j < 8; j++) {                                 \
                int n0 = wn * 64 + j * 8;                                 \
                bf[j][0] = Ws[b][n0 + g][ks + t];                         \
                bf[j][1] = Ws[b][n0 + g][ks + t + 4];                     \
            }                                                             \
            _Pragma("unroll")                                             \
            for (int i = 0; i < 2; i++)                                   \
                _Pragma("unroll")                                         \
                for (int j = 0; j < 8; j++)                               \
                    mma_tf32(acc[i][j], af[i], bf[j]);                    \
        }                                                                 \
    }

    LOADG(0);
    STORES(0);
    __syncthreads();

    int buf = 0;
    for (int k0 = 16; k0 < K; k0 += 16) {
        LOADG(k0);
        COMPUTE(buf);
        STORES(buf ^ 1);
        __syncthreads();
        buf ^= 1;
    }
    COMPUTE(buf);

    // epilogue
#pragma unroll
    for (int i = 0; i < 2; i++) {
#pragma unroll
        for (int j = 0; j < 8; j++) {
            int col = col0 + wn * 64 + j * 8 + 2 * t;
            if (col >= N) continue;
            float bv = (MODE != 0) ? bias[col]     : 0.f;
            float bv1 = (MODE != 0) ? bias[col + 1] : 0.f;
#pragma unroll
            for (int h = 0; h < 2; h++) {
                int row = row0 + wm * 32 + i * 16 + g + h * 8;
                size_t oidx = (size_t)row * N + col;
                float v0 = acc[i][j][2 * h + 0];
                float v1 = acc[i][j][2 * h + 1];
                if (MODE == 1) { v0 = gelu_tanh_f(v0 + bv); v1 = gelu_tanh_f(v1 + bv1); }
                else if (MODE == 2) {
                    float2 rr = *(const float2*)(resid + oidx);
                    v0 = rr.x + v0 + bv; v1 = rr.y + v1 + bv1;
                }
                else if (MODE == 3) { v0 = softplus_f(v0 + bv); v1 = softplus_f(v1 + bv1); }
                float2 ov = make_float2(v0, v1);
                *(float2*)(C + oidx) = ov;
            }
        }
    }
#undef LOADG
#undef STORES
#undef COMPUTE
}

// ---------------- depthwise causal conv (D_CONV=4) + silu -------------------
__global__ __launch_bounds__(256) void conv_silu_kernel(
    const float* __restrict__ XZ, const float* __restrict__ conv_w,
    const float* __restrict__ conv_b, float* __restrict__ XC)
{
    size_t idx = (size_t)blockIdx.x * blockDim.x + threadIdx.x;
    if (idx >= (size_t)MM * DI) return;
    int d = (int)(idx & (DI - 1));
    int m = (int)(idx >> 10);
    int t = m & (LL - 1);
    int mb = m - t;                       // batch base row
    float acc = conv_b[d];
#pragma unroll
    for (int k = 0; k < 4; k++) {
        int tt = t - 3 + k;
        if (tt >= 0)
            acc = fmaf(conv_w[d * 4 + k], XZ[(size_t)(mb + tt) * (2 * DI) + d], acc);
    }
    XC[idx] = silu_f(acc);
}

// ---------------- selective scan: warp per (b,d) ----------------------------
__global__ __launch_bounds__(256) void scan_kernel(
    const float* __restrict__ DT, const float* __restrict__ XC,
    const float* __restrict__ PROJ, const float* __restrict__ XZ,
    const float* __restrict__ A_log, const float* __restrict__ D_param,
    float* __restrict__ Y)
{
    int wg = (blockIdx.x * blockDim.x + threadIdx.x) >> 5;  // 0..2047
    int lane = threadIdx.x & 31;
    int b = wg >> 10;
    int d = wg & (DI - 1);
    bool act = lane < NS;
    float A_n = act ? -expf(A_log[d * NS + lane]) : 0.f;
    float Dp = D_param[d];

    const float* dtp = DT + (size_t)b * LL * DI + d;
    const float* xcp = XC + (size_t)b * LL * DI + d;
    const float* zp  = XZ + (size_t)b * LL * (2 * DI) + DI + d;
    const float* bcp = PROJ + (size_t)b * LL * PROJC + RR;
    float* yp = Y + (size_t)b * LL * DI + d;

    float h = 0.f;
    for (int t = 0; t < LL; t++) {
        float dt = __ldg(dtp);
        float xc = __ldg(xcp);
        float zv = __ldg(zp);
        float bcv = __ldg(bcp + lane);        // lanes 0-15: B[n], 16-31: C[n]
        float Cv = __shfl_down_sync(0xffffffffu, bcv, 16);
        float Bv = act ? bcv : 0.f;
        Cv = act ? Cv : 0.f;

        float dA = __expf(dt * A_n);
        h = fmaf(dA, h, dt * xc * Bv);
        float part = h * Cv;                   // nonzero only in lanes 0-15
#pragma unroll
        for (int o = 8; o; o >>= 1) part += __shfl_xor_sync(0xffffffffu, part, o);
        if (lane == 0) {
            float y = part + Dp * xc;
            *yp = y * silu_f(zv);
        }
        dtp += DI; xcp += DI; zp += 2 * DI; bcp += PROJC; yp += DI;
    }
}

// ---------------- residual add with gather ----------------------------------
__global__ __launch_bounds__(256) void add_gather_kernel(
    const float* __restrict__ X, const float* __restrict__ OUTP,
    const int* __restrict__ path_rev, float* __restrict__ XNEW)
{
    size_t idx = (size_t)blockIdx.x * blockDim.x + threadIdx.x;
    if (idx >= (size_t)MM * DD) return;
    int d = (int)(idx & (DD - 1));
    int m = (int)(idx >> 10);
    int b = m >> 12, t = m & (LL - 1);
    int src = (b << 12) + path_rev[t];
    XNEW[idx] = X[idx] + OUTP[(size_t)src * DD + d];
}

// ---------------- launch -----------------------------------------------------
extern "C" void kernel_launch(void* const* d_in, const int* in_sizes, int n_in,
                              void* d_out, int out_size)
{
    const float* x          = (const float*)d_in[0];
    const int*   path       = (const int*)  d_in[1];
    const int*   path_rev   = (const int*)  d_in[2];
    const float* in_proj_w  = (const float*)d_in[3];
    const float* conv_w     = (const float*)d_in[4];
    const float* conv_b     = (const float*)d_in[5];
    const float* x_proj_w   = (const float*)d_in[6];
    const float* dt_proj_w  = (const float*)d_in[7];
    const float* dt_proj_b  = (const float*)d_in[8];
    const float* A_log      = (const float*)d_in[9];
    const float* D_param    = (const float*)d_in[10];
    const float* out_proj_w = (const float*)d_in[11];
    const float* fc1_w      = (const float*)d_in[12];
    const float* fc1_b      = (const float*)d_in[13];
    const float* fc2_w      = (const float*)d_in[14];
    const float* fc2_b      = (const float*)d_in[15];
    float* out = (float*)d_out;

    float *U, *XZ, *XC, *PROJ, *DT, *Y, *OUTP, *XNEW, *HN, *G;
    cudaGetSymbolAddress((void**)&U,    g_U);
    cudaGetSymbolAddress((void**)&XZ,   g_XZ);
    cudaGetSymbolAddress((void**)&XC,   g_XC);
    cudaGetSymbolAddress((void**)&PROJ, g_PROJ);
    cudaGetSymbolAddress((void**)&DT,   g_DT);
    cudaGetSymbolAddress((void**)&Y,    g_Y);
    cudaGetSymbolAddress((void**)&OUTP, g_OUTP);
    cudaGetSymbolAddress((void**)&XNEW, g_XNEW);
    cudaGetSymbolAddress((void**)&HN,   g_HN);
    cudaGetSymbolAddress((void**)&G,    g_G);

    // 1. u = LN(x[:, path, :])
    ln_kernel<<<MM, 256>>>(x, path, U);

    // 2. xz = u @ in_proj_w^T   (8192 x 2048, K=1024)
    mma_gemm<0><<<dim3(2 * DI / 128, MM / 128), 256>>>(U, DD, in_proj_w, nullptr, nullptr, XZ, MM, 2 * DI, DD);

    // 3. conv + silu
    conv_silu_kernel<<<(int)(((size_t)MM * DI + 255) / 256), 256>>>(XZ, conv_w, conv_b, XC);

    // 4. proj = xc @ x_proj_w^T   (8192 x 96, K=1024)
    mma_gemm<0><<<dim3(1, MM / 128), 256>>>(XC, DI, x_proj_w, nullptr, nullptr, PROJ, MM, PROJC, DI);

    // 5. dt = softplus(proj[:, :64] @ dt_proj_w^T + b)   (8192 x 1024, K=64, lda=96)
    mma_gemm<3><<<dim3(DI / 128, MM / 128), 256>>>(PROJ, PROJC, dt_proj_w, dt_proj_b, nullptr, DT, MM, DI, RR);

    // 6. selective scan -> Y = (scan + D*xc) * silu(z)
    scan_kernel<<<(BB * DI * 32) / 256, 256>>>(DT, XC, PROJ, XZ, A_log, D_param, Y);

    // 7. OUTP = Y @ out_proj_w^T   (8192 x 1024, K=1024)
    mma_gemm<0><<<dim3(DD / 128, MM / 128), 256>>>(Y, DI, out_proj_w, nullptr, nullptr, OUTP, MM, DD, DI);

    // 8. xnew = x + OUTP[:, path_rev, :]
    add_gather_kernel<<<(int)(((size_t)MM * DD + 255) / 256), 256>>>(x, OUTP, path_rev, XNEW);

    // 9. hn = LN(xnew)
    ln_kernel<<<MM, 256>>>(XNEW, nullptr, HN);

    // 10. G = gelu(hn @ fc1_w^T + fc1_b)   (8192 x 4096, K=1024)
    mma_gemm<1><<<dim3(HH / 128, MM / 128), 256>>>(HN, DD, fc1_w, fc1_b, nullptr, G, MM, HH, DD);

    // 11. out = xnew + G @ fc2_w^T + fc2_b   (8192 x 1024, K=4096)
    mma_gemm<2><<<dim3(DD / 128, MM / 128), 256>>>(G, HH, fc2_w, fc2_b, XNEW, out, MM, DD, HH);
}

// round 4
// speedup vs baseline: 4.8152x; 2.1564x over previous
#include <cuda_runtime.h>
#include <cuda_fp16.h>
#include <cstdint>

// Problem constants (fixed by setup_inputs)
#define BB 2
#define LL 4096
#define DD 1024
#define DI 1024
#define NS 16
#define RR 64
#define HH 4096
#define MM (BB*LL)          // 8192 rows
#define PROJC (RR + 2*NS)   // 96

// ---------------- scratch ( __device__ globals, no allocation ) -------------
__device__ __half g_Uh  [(size_t)MM * DD];      // LN(gathered x), fp16
__device__ float  g_XZ  [(size_t)MM * 2 * DI];  // in_proj output (xi | z)
__device__ float  g_XC  [(size_t)MM * DI];      // conv + silu (f32 for scan)
__device__ __half g_XCh [(size_t)MM * DI];      // conv + silu (f16 for GEMM)
__device__ float  g_PROJ[(size_t)MM * PROJC];   // x_proj output (f32 for scan B,C)
__device__ __half g_PROJh[(size_t)MM * PROJC];  // fp16 copy for dt GEMM
__device__ float  g_DT  [(size_t)MM * DI];      // softplus(dt)
__device__ __half g_Yh  [(size_t)MM * DI];      // scan output * silu(z), fp16
__device__ float  g_OUTP[(size_t)MM * DD];      // out_proj output
__device__ float  g_XNEW[(size_t)MM * DD];      // x + scattered mamba out
__device__ __half g_HNh [(size_t)MM * DD];      // LN(xnew), fp16
__device__ __half g_Gh  [(size_t)MM * HH];      // gelu(fc1), fp16
// fp16 weights
__device__ __half g_Wip [(size_t)2 * DI * DD];  // in_proj
__device__ __half g_Wxp [(size_t)PROJC * DI];   // x_proj
__device__ __half g_Wdt [(size_t)DI * RR];      // dt_proj
__device__ __half g_Wop [(size_t)DD * DI];      // out_proj
__device__ __half g_Wf1 [(size_t)HH * DD];      // fc1
__device__ __half g_Wf2 [(size_t)DD * HH];      // fc2

// ---------------- helpers ---------------------------------------------------
__device__ __forceinline__ float silu_f(float x) {
    return x / (1.0f + __expf(-x));
}
__device__ __forceinline__ float gelu_tanh_f(float x) {
    float u = 0.7978845608028654f * (x + 0.044715f * x * x * x);
    return 0.5f * x * (1.0f + tanhf(u));
}
__device__ __forceinline__ float softplus_f(float x) {
    return (x > 20.0f) ? x : log1pf(expf(x));
}

// ---------------- f32 -> f16 convert ----------------------------------------
__global__ __launch_bounds__(256) void f2h_kernel(const float* __restrict__ s,
                                                  __half* __restrict__ d, int n)
{
    int i = (blockIdx.x * blockDim.x + threadIdx.x) * 4;
    if (i >= n) return;
    float4 v = *(const float4*)(s + i);
    __half2* dp = (__half2*)(d + i);
    dp[0] = __floats2half2_rn(v.x, v.y);
    dp[1] = __floats2half2_rn(v.z, v.w);
}

// ---------------- LayerNorm (optional gather), fp16 out ---------------------
__global__ __launch_bounds__(256) void ln_kernel(
    const float* __restrict__ X, const int* __restrict__ gather,
    __half* __restrict__ Out)
{
    int row = blockIdx.x;                 // 0..MM-1
    int b = row >> 12, t = row & (LL - 1);
    int src = gather ? ((b << 12) + gather[t]) : row;
    const float* xp = X + (size_t)src * DD;
    __half* op = Out + (size_t)row * DD;
    __shared__ float sred[8];
    __shared__ float smv[2];
    int tid = threadIdx.x;

    float v[4];
    float s = 0.f;
#pragma unroll
    for (int i = 0; i < 4; i++) { v[i] = xp[tid + i * 256]; s += v[i]; }
#pragma unroll
    for (int o = 16; o; o >>= 1) s += __shfl_xor_sync(0xffffffffu, s, o);
    if ((tid & 31) == 0) sred[tid >> 5] = s;
    __syncthreads();
    if (tid < 8) {
        s = sred[tid];
#pragma unroll
        for (int o = 4; o; o >>= 1) s += __shfl_xor_sync(0xffu, s, o);
        if (tid == 0) smv[0] = s * (1.0f / DD);
    }
    __syncthreads();
    float mean = smv[0];
    float vs = 0.f;
#pragma unroll
    for (int i = 0; i < 4; i++) { float d = v[i] - mean; vs += d * d; }
#pragma unroll
    for (int o = 16; o; o >>= 1) vs += __shfl_xor_sync(0xffffffffu, vs, o);
    __syncthreads();
    if ((tid & 31) == 0) sred[tid >> 5] = vs;
    __syncthreads();
    if (tid < 8) {
        vs = sred[tid];
#pragma unroll
        for (int o = 4; o; o >>= 1) vs += __shfl_xor_sync(0xffu, vs, o);
        if (tid == 0) smv[1] = rsqrtf(vs * (1.0f / DD) + 1e-6f);
    }
    __syncthreads();
    float inv = smv[1];
#pragma unroll
    for (int i = 0; i < 4; i++) op[tid + i * 256] = __float2half((v[i] - mean) * inv);
}

// ---------------- FP16 tensor-core GEMM -------------------------------------
// C[m,n] = epi( sum_k A[m,k]*W[n,k] ), A: MxK half (lda), W: NxK half row-major.
// MODE 0: f32 out   1: gelu(acc+bias)->f16 out   2: resid+acc+bias->f32 out
// MODE 3: softplus(acc+bias)->f32 out            4: dual f32 + f16 out
// Tile 128x128, BK=32 halfs, 8 warps (4m x 2n), warp tile 32x64.
// cp.async double-buffered smem, ldmatrix.x4 A frags, m16n8k16 mma.

#define BKH 32
#define ROWH 40   // 32 + 8 pad halfs (80B rows: conflict-free for ldmatrix & b32 loads)

__device__ __forceinline__ void mma_f16(float c[4], const uint32_t a[4], const uint32_t b[2]) {
    asm volatile(
        "mma.sync.aligned.m16n8k16.row.col.f32.f16.f16.f32 "
        "{%0,%1,%2,%3}, {%4,%5,%6,%7}, {%8,%9}, {%0,%1,%2,%3};\n"
        : "+f"(c[0]), "+f"(c[1]), "+f"(c[2]), "+f"(c[3])
        : "r"(a[0]), "r"(a[1]), "r"(a[2]), "r"(a[3]), "r"(b[0]), "r"(b[1]));
}
__device__ __forceinline__ void ldsm_x4(uint32_t r[4], const void* p) {
    uint32_t s = (uint32_t)__cvta_generic_to_shared(p);
    asm volatile("ldmatrix.sync.aligned.m8n8.x4.shared.b16 {%0,%1,%2,%3}, [%4];\n"
                 : "=r"(r[0]), "=r"(r[1]), "=r"(r[2]), "=r"(r[3]) : "r"(s));
}
__device__ __forceinline__ void cp16(void* dst, const void* src, bool pred) {
    uint32_t d = (uint32_t)__cvta_generic_to_shared(dst);
    int sz = pred ? 16 : 0;
    asm volatile("cp.async.cg.shared.global [%0], [%1], 16, %2;\n"
                 :: "r"(d), "l"(src), "r"(sz));
}

template <int MODE>
__global__ __launch_bounds__(256, 2) void hgemm(
    const __half* __restrict__ A, int lda,
    const __half* __restrict__ W,
    const float* __restrict__ bias,
    const float* __restrict__ resid,
    float* __restrict__ Cf, __half* __restrict__ Ch,
    int M, int N, int K)
{
    __shared__ __half As[2][128][ROWH];
    __shared__ __half Ws[2][128][ROWH];

    int tid  = threadIdx.x;
    int warp = tid >> 5, lane = tid & 31;
    int g = lane >> 2, t = lane & 3;
    int wm = warp >> 1, wn = warp & 1;     // 4 x 2 warp grid
    int row0 = blockIdx.y * 128;
    int col0 = blockIdx.x * 128;

    // global->smem mapping: thread -> (row = tid>>1), two 16B chunks
    int lrow = tid >> 1;
    int lch  = (tid & 1) * 16;             // half offset of first chunk
    const __half* Ag = A + (size_t)(row0 + lrow) * lda + lch;
    int wnrow = col0 + lrow;
    bool wok = (wnrow < N);
    const __half* Wg = W + (size_t)(wok ? wnrow : 0) * K + lch;

    float acc[2][8][4];
#pragma unroll
    for (int i = 0; i < 2; i++)
#pragma unroll
        for (int j = 0; j < 8; j++)
#pragma unroll
            for (int q = 0; q < 4; q++) acc[i][j][q] = 0.f;

#define LOADST(k0, b)                                                     \
    {                                                                     \
        cp16(&As[b][lrow][lch + 0], Ag + (k0) + 0, true);                 \
        cp16(&As[b][lrow][lch + 8], Ag + (k0) + 8, true);                 \
        cp16(&Ws[b][lrow][lch + 0], Wg + (k0) + 0, wok);                  \
        cp16(&Ws[b][lrow][lch + 8], Wg + (k0) + 8, wok);                  \
        asm volatile("cp.async.commit_group;\n");                         \
    }

#define COMPUTE(b)                                                        \
    {                                                                     \
        _Pragma("unroll")                                                 \
        for (int ks = 0; ks < BKH; ks += 16) {                            \
            uint32_t af[2][4], bf[8][2];                                  \
            _Pragma("unroll")                                             \
            for (int i = 0; i < 2; i++)                                   \
                ldsm_x4(af[i], &As[b][wm * 32 + i * 16 + (lane & 15)]     \
                                   [ks + (lane >> 4) * 8]);               \
            _Pragma("unroll")                                             \
            for (int j = 0; j < 8; j++) {                                 \
                const __half* wp = &Ws[b][wn * 64 + j * 8 + g][ks + 2*t]; \
                bf[j][0] = *(const uint32_t*)wp;                          \
                bf[j][1] = *(const uint32_t*)(wp + 8);                    \
            }                                                             \
            _Pragma("unroll")                                             \
            for (int i = 0; i < 2; i++)                                   \
                _Pragma("unroll")                                         \
                for (int j = 0; j < 8; j++)                               \
                    mma_f16(acc[i][j], af[i], bf[j]);                     \
        }                                                                 \
    }

    LOADST(0, 0);
    int buf = 0;
    for (int k0 = BKH; k0 < K; k0 += BKH) {
        LOADST(k0, buf ^ 1);
        asm volatile("cp.async.wait_group 1;\n");
        __syncthreads();
        COMPUTE(buf);
        __syncthreads();
        buf ^= 1;
    }
    asm volatile("cp.async.wait_group 0;\n");
    __syncthreads();
    COMPUTE(buf);

    // epilogue: each thread owns cols (2t, 2t+1), rows g / g+8 per 16-row tile
#pragma unroll
    for (int i = 0; i < 2; i++) {
#pragma unroll
        for (int j = 0; j < 8; j++) {
            int col = col0 + wn * 64 + j * 8 + 2 * t;
            if (col >= N) continue;
            float b0v = 0.f, b1v = 0.f;
            if (MODE == 1 || MODE == 2 || MODE == 3) { b0v = bias[col]; b1v = bias[col + 1]; }
#pragma unroll
            for (int h = 0; h < 2; h++) {
                int row = row0 + wm * 32 + i * 16 + g + h * 8;
                size_t oidx = (size_t)row * N + col;
                float v0 = acc[i][j][2 * h + 0];
                float v1 = acc[i][j][2 * h + 1];
                if (MODE == 1) {
                    v0 = gelu_tanh_f(v0 + b0v); v1 = gelu_tanh_f(v1 + b1v);
                    *(__half2*)(Ch + oidx) = __floats2half2_rn(v0, v1);
                } else if (MODE == 2) {
                    float2 rr = *(const float2*)(resid + oidx);
                    *(float2*)(Cf + oidx) = make_float2(rr.x + v0 + b0v, rr.y + v1 + b1v);
                } else if (MODE == 3) {
                    *(float2*)(Cf + oidx) = make_float2(softplus_f(v0 + b0v), softplus_f(v1 + b1v));
                } else if (MODE == 4) {
                    *(float2*)(Cf + oidx) = make_float2(v0, v1);
                    *(__half2*)(Ch + oidx) = __floats2half2_rn(v0, v1);
                } else {
                    *(float2*)(Cf + oidx) = make_float2(v0, v1);
                }
            }
        }
    }
#undef LOADST
#undef COMPUTE
}

// ---------------- depthwise causal conv (D_CONV=4) + silu -------------------
__global__ __launch_bounds__(256) void conv_silu_kernel(
    const float* __restrict__ XZ, const float* __restrict__ conv_w,
    const float* __restrict__ conv_b, float* __restrict__ XC,
    __half* __restrict__ XCh)
{
    size_t idx = (size_t)blockIdx.x * blockDim.x + threadIdx.x;
    if (idx >= (size_t)MM * DI) return;
    int d = (int)(idx & (DI - 1));
    int m = (int)(idx >> 10);
    int t = m & (LL - 1);
    int mb = m - t;                       // batch base row
    float acc = conv_b[d];
#pragma unroll
    for (int k = 0; k < 4; k++) {
        int tt = t - 3 + k;
        if (tt >= 0)
            acc = fmaf(conv_w[d * 4 + k], XZ[(size_t)(mb + tt) * (2 * DI) + d], acc);
    }
    float r = silu_f(acc);
    XC[idx] = r;
    XCh[idx] = __float2half(r);
}

// ---------------- selective scan: warp per (b,d), prefetched -----------------
__global__ __launch_bounds__(256) void scan_kernel(
    const float* __restrict__ DT, const float* __restrict__ XC,
    const float* __restrict__ PROJ, const float* __restrict__ XZ,
    const float* __restrict__ A_log, const float* __restrict__ D_param,
    __half* __restrict__ Y)
{
    int wg = (blockIdx.x * blockDim.x + threadIdx.x) >> 5;  // 0..2047
    int lane = threadIdx.x & 31;
    int b = wg >> 10;
    int d = wg & (DI - 1);
    bool act = lane < NS;
    float A_n = act ? -expf(A_log[d * NS + lane]) : 0.f;
    float Dp = D_param[d];

    const float* dtp = DT + (size_t)b * LL * DI + d;
    const float* xcp = XC + (size_t)b * LL * DI + d;
    const float* zp  = XZ + (size_t)b * LL * (2 * DI) + DI + d;
    const float* bcp = PROJ + (size_t)b * LL * PROJC + RR;
    __half* yp = Y + (size_t)b * LL * DI + d;

    float h = 0.f;
    float dt = __ldg(dtp), xc = __ldg(xcp), zv = __ldg(zp), bcv = __ldg(bcp + lane);
    for (int t = 0; t < LL; t++) {
        // prefetch next step while current recurrence computes
        float ndt = 0.f, nxc = 0.f, nzv = 0.f, nbcv = 0.f;
        if (t + 1 < LL) {
            ndt = __ldg(dtp + DI);
            nxc = __ldg(xcp + DI);
            nzv = __ldg(zp + 2 * DI);
            nbcv = __ldg(bcp + PROJC + lane);
        }
        float Cv = __shfl_down_sync(0xffffffffu, bcv, 16);
        float Bv = act ? bcv : 0.f;
        Cv = act ? Cv : 0.f;

        float dA = __expf(dt * A_n);
        h = fmaf(dA, h, dt * xc * Bv);
        float part = h * Cv;                   // nonzero only in lanes 0-15
#pragma unroll
        for (int o = 8; o; o >>= 1) part += __shfl_xor_sync(0xffffffffu, part, o);
        if (lane == 0) {
            float y = part + Dp * xc;
            *yp = __float2half(y * silu_f(zv));
        }
        dtp += DI; xcp += DI; zp += 2 * DI; bcp += PROJC; yp += DI;
        dt = ndt; xc = nxc; zv = nzv; bcv = nbcv;
    }
}

// ---------------- residual add with gather ----------------------------------
__global__ __launch_bounds__(256) void add_gather_kernel(
    const float* __restrict__ X, const float* __restrict__ OUTP,
    const int* __restrict__ path_rev, float* __restrict__ XNEW)
{
    size_t idx = (size_t)blockIdx.x * blockDim.x + threadIdx.x;
    if (idx >= (size_t)MM * DD) return;
    int d = (int)(idx & (DD - 1));
    int m = (int)(idx >> 10);
    int b = m >> 12, t = m & (LL - 1);
    int src = (b << 12) + path_rev[t];
    XNEW[idx] = X[idx] + OUTP[(size_t)src * DD + d];
}

// ---------------- launch -----------------------------------------------------
extern "C" void kernel_launch(void* const* d_in, const int* in_sizes, int n_in,
                              void* d_out, int out_size)
{
    const float* x          = (const float*)d_in[0];
    const int*   path       = (const int*)  d_in[1];
    const int*   path_rev   = (const int*)  d_in[2];
    const float* in_proj_w  = (const float*)d_in[3];
    const float* conv_w     = (const float*)d_in[4];
    const float* conv_b     = (const float*)d_in[5];
    const float* x_proj_w   = (const float*)d_in[6];
    const float* dt_proj_w  = (const float*)d_in[7];
    const float* dt_proj_b  = (const float*)d_in[8];
    const float* A_log      = (const float*)d_in[9];
    const float* D_param    = (const float*)d_in[10];
    const float* out_proj_w = (const float*)d_in[11];
    const float* fc1_w      = (const float*)d_in[12];
    const float* fc1_b      = (const float*)d_in[13];
    const float* fc2_w      = (const float*)d_in[14];
    const float* fc2_b      = (const float*)d_in[15];
    float* out = (float*)d_out;

    __half *Uh, *XCh, *PROJh, *Yh, *HNh, *Gh;
    __half *Wip, *Wxp, *Wdt, *Wop, *Wf1, *Wf2;
    float *XZ, *XC, *PROJ, *DT, *OUTP, *XNEW;
    cudaGetSymbolAddress((void**)&Uh,    g_Uh);
    cudaGetSymbolAddress((void**)&XZ,    g_XZ);
    cudaGetSymbolAddress((void**)&XC,    g_XC);
    cudaGetSymbolAddress((void**)&XCh,   g_XCh);
    cudaGetSymbolAddress((void**)&PROJ,  g_PROJ);
    cudaGetSymbolAddress((void**)&PROJh, g_PROJh);
    cudaGetSymbolAddress((void**)&DT,    g_DT);
    cudaGetSymbolAddress((void**)&Yh,    g_Yh);
    cudaGetSymbolAddress((void**)&OUTP,  g_OUTP);
    cudaGetSymbolAddress((void**)&XNEW,  g_XNEW);
    cudaGetSymbolAddress((void**)&HNh,   g_HNh);
    cudaGetSymbolAddress((void**)&Gh,    g_Gh);
    cudaGetSymbolAddress((void**)&Wip,   g_Wip);
    cudaGetSymbolAddress((void**)&Wxp,   g_Wxp);
    cudaGetSymbolAddress((void**)&Wdt,   g_Wdt);
    cudaGetSymbolAddress((void**)&Wop,   g_Wop);
    cudaGetSymbolAddress((void**)&Wf1,   g_Wf1);
    cudaGetSymbolAddress((void**)&Wf2,   g_Wf2);

    // 0. weights -> fp16
    auto cvt = [&](const float* s, __half* d, int n) {
        f2h_kernel<<<(n / 4 + 255) / 256, 256>>>(s, d, n);
    };
    cvt(in_proj_w,  Wip, 2 * DI * DD);
    cvt(x_proj_w,   Wxp, PROJC * DI);
    cvt(dt_proj_w,  Wdt, DI * RR);
    cvt(out_proj_w, Wop, DD * DI);
    cvt(fc1_w,      Wf1, HH * DD);
    cvt(fc2_w,      Wf2, DD * HH);

    // 1. u = LN(x[:, path, :]) -> fp16
    ln_kernel<<<MM, 256>>>(x, path, Uh);

    // 2. xz = u @ in_proj_w^T   (8192 x 2048, K=1024) -> f32
    hgemm<0><<<dim3(2 * DI / 128, MM / 128), 256>>>(Uh, DD, Wip, nullptr, nullptr, XZ, nullptr, MM, 2 * DI, DD);

    // 3. conv + silu -> f32 + f16
    conv_silu_kernel<<<(int)(((size_t)MM * DI + 255) / 256), 256>>>(XZ, conv_w, conv_b, XC, XCh);

    // 4. proj = xc @ x_proj_w^T   (8192 x 96, K=1024) -> f32 + f16
    hgemm<4><<<dim3(1, MM / 128), 256>>>(XCh, DI, Wxp, nullptr, nullptr, PROJ, PROJh, MM, PROJC, DI);

    // 5. dt = softplus(proj[:, :64] @ dt_proj_w^T + b)   (8192 x 1024, K=64)
    hgemm<3><<<dim3(DI / 128, MM / 128), 256>>>(PROJh, PROJC, Wdt, dt_proj_b, nullptr, DT, nullptr, MM, DI, RR);

    // 6. selective scan -> Yh = ((scan + D*xc) * silu(z)) fp16
    scan_kernel<<<(BB * DI * 32) / 256, 256>>>(DT, XC, PROJ, XZ, A_log, D_param, Yh);

    // 7. OUTP = Y @ out_proj_w^T   (8192 x 1024, K=1024) -> f32
    hgemm<0><<<dim3(DD / 128, MM / 128), 256>>>(Yh, DI, Wop, nullptr, nullptr, OUTP, nullptr, MM, DD, DI);

    // 8. xnew = x + OUTP[:, path_rev, :]
    add_gather_kernel<<<(int)(((size_t)MM * DD + 255) / 256), 256>>>(x, OUTP, path_rev, XNEW);

    // 9. hn = LN(xnew) -> fp16
    ln_kernel<<<MM, 256>>>(XNEW, nullptr, HNh);

    // 10. G = gelu(hn @ fc1_w^T + fc1_b)   (8192 x 4096, K=1024) -> fp16
    hgemm<1><<<dim3(HH / 128, MM / 128), 256>>>(HNh, DD, Wf1, fc1_b, nullptr, nullptr, Gh, MM, HH, DD);

    // 11. out = xnew + G @ fc2_w^T + fc2_b   (8192 x 1024, K=4096) -> f32
    hgemm<2><<<dim3(DD / 128, MM / 128), 256>>>(Gh, HH, Wf2, fc2_b, XNEW, out, nullptr, MM, DD, HH);
}